// round 4
// baseline (speedup 1.0000x reference)
#include <cuda_runtime.h>
#include <math.h>

// ---------------------------------------------------------------------------
// Problem constants (shapes fixed by the reference)
// ---------------------------------------------------------------------------
#define MAXN   50000
#define INDIM  128
#define HID    32
#define H1     4
#define C1     128          // H1*HID
#define AGENTS 32
#define NEG    0.2f

// ---------------------------------------------------------------------------
// Device scratch (static globals — allocations are forbidden)
// ---------------------------------------------------------------------------
__device__ __align__(16) float g_h1 [MAXN * C1];     // layer1 pre-attention features
__device__ __align__(16) float g_x1 [MAXN * C1];     // layer1 aggregate -> elu -> layer2 input
__device__ __align__(16) float g_as1[MAXN * H1];
__device__ __align__(16) float g_ad1[MAXN * H1];
__device__ __align__(16) float g_den1[MAXN * H1];
__device__ __align__(16) float g_h2 [MAXN * HID];
__device__ __align__(16) float g_o2 [MAXN * HID];    // layer2 aggregate -> elu
__device__ float g_as2[MAXN];
__device__ float g_ad2[MAXN];
__device__ float g_den2[MAXN];
__device__ int   g_is64;

// ---------------------------------------------------------------------------
// Helpers
// ---------------------------------------------------------------------------
__device__ __forceinline__ float lrelu(float v) { return v > 0.f ? v : NEG * v; }

__device__ __forceinline__ void red_add_v4(float* p, float4 v) {
    unsigned long long gp = (unsigned long long)__cvta_generic_to_global((void*)p);
    asm volatile("red.global.add.v4.f32 [%0], {%1,%2,%3,%4};"
                 :: "l"(gp), "f"(v.x), "f"(v.y), "f"(v.z), "f"(v.w) : "memory");
}

__device__ __forceinline__ void load_edge(const void* __restrict__ ei, int i, int E,
                                          int& s, int& d) {
    if (i >= E) { s = d = i - E; return; }
    if (g_is64) {
        const long long* p = (const long long*)ei;
        s = (int)p[i]; d = (int)p[E + i];
    } else {
        const int* p = (const int*)ei;
        s = p[i]; d = p[E + i];
    }
}

// ---------------------------------------------------------------------------
// edge_index dtype probe: int64 values < 2^31 -> every odd 32-bit word is 0.
// ---------------------------------------------------------------------------
__global__ void detect_i64_kernel(const unsigned int* __restrict__ w) {
    int allz = 1;
    for (int i = 0; i < 16; i++)
        if (w[2 * i + 1] != 0u) allz = 0;
    g_is64 = allz;
}

// ---------------------------------------------------------------------------
// Zero the accumulation scratch + the value cell of d_out.
// ---------------------------------------------------------------------------
__global__ void zero_scratch_kernel(float* __restrict__ out, int Nn) {
    long long nA = (long long)Nn * C1;          // g_x1
    long long nB = (long long)Nn * H1;          // g_den1
    long long nC = (long long)Nn * HID;         // g_o2
    long long nD = (long long)Nn;               // g_den2
    long long total = nA + nB + nC + nD;
    for (long long i = (long long)blockIdx.x * blockDim.x + threadIdx.x;
         i < total; i += (long long)gridDim.x * blockDim.x) {
        long long j = i;
        if (j < nA) { g_x1[j] = 0.f; continue; }
        j -= nA;
        if (j < nB) { g_den1[j] = 0.f; continue; }
        j -= nB;
        if (j < nC) { g_o2[j] = 0.f; continue; }
        j -= nC;
        g_den2[j] = 0.f;
    }
    if (blockIdx.x == 0 && threadIdx.x == 0)
        out[(long long)AGENTS * Nn] = 0.f;
}

// ---------------------------------------------------------------------------
// GEMM1: h1 = x @ W1  ([N,128]x[128,128]) fused with a_s/a_d reductions.
// Block = 128 threads (thread t = output column t), 16 nodes / block.
// ---------------------------------------------------------------------------
__global__ __launch_bounds__(128) void gemm1_kernel(
    const float* __restrict__ x, const float* __restrict__ W1,
    const float* __restrict__ a1s, const float* __restrict__ a1d, int Nn) {
    __shared__ float xs[16][INDIM];
    int t  = threadIdx.x;
    int n0 = blockIdx.x * 16;

    const float4* xv = (const float4*)x;
    for (int i = t; i < 16 * 32; i += 128) {
        int m = i >> 5, c = i & 31;
        int n = n0 + m;
        float4 v = (n < Nn) ? xv[(long long)n * 32 + c] : make_float4(0.f, 0.f, 0.f, 0.f);
        ((float4*)(&xs[0][0]))[m * 32 + c] = v;
    }
    __syncthreads();

    float acc[16];
#pragma unroll
    for (int m = 0; m < 16; m++) acc[m] = 0.f;

    for (int kt = 0; kt < INDIM; kt += 16) {
        float w[16];
#pragma unroll
        for (int j = 0; j < 16; j++) w[j] = W1[(kt + j) * C1 + t];
#pragma unroll
        for (int m = 0; m < 16; m++) {
            const float4* xr = (const float4*)&xs[m][kt];
            float4 x0 = xr[0], x1 = xr[1], x2 = xr[2], x3 = xr[3];
            acc[m] += x0.x * w[0]  + x0.y * w[1]  + x0.z * w[2]  + x0.w * w[3]
                    + x1.x * w[4]  + x1.y * w[5]  + x1.z * w[6]  + x1.w * w[7]
                    + x2.x * w[8]  + x2.y * w[9]  + x2.z * w[10] + x2.w * w[11]
                    + x3.x * w[12] + x3.y * w[13] + x3.z * w[14] + x3.w * w[15];
        }
    }

    float asv = a1s[t], adv = a1d[t];
    int lane = t & 31;
    int head = t >> 5;          // warp w <-> head w (32 consecutive cols per head)
#pragma unroll
    for (int m = 0; m < 16; m++) {
        int n = n0 + m;
        if (n < Nn) g_h1[(long long)n * C1 + t] = acc[m];
        float s = acc[m] * asv;
        float d = acc[m] * adv;
#pragma unroll
        for (int off = 16; off; off >>= 1) {
            s += __shfl_down_sync(0xffffffffu, s, off);
            d += __shfl_down_sync(0xffffffffu, d, off);
        }
        if (lane == 0 && n < Nn) {
            g_as1[n * H1 + head] = s;
            g_ad1[n * H1 + head] = d;
        }
    }
}

// ---------------------------------------------------------------------------
// Layer1 softmax denominators: 1 thread / edge, 4 heads, one v4 RED.
// ---------------------------------------------------------------------------
__global__ void edge_den1_kernel(const void* __restrict__ ei, int E, int etot) {
    int i = blockIdx.x * blockDim.x + threadIdx.x;
    if (i >= etot) return;
    int s, d;
    load_edge(ei, i, E, s, d);
    float4 av = *(const float4*)(g_as1 + s * H1);
    float4 dv = *(const float4*)(g_ad1 + d * H1);
    float4 ex;
    ex.x = __expf(lrelu(av.x + dv.x));
    ex.y = __expf(lrelu(av.y + dv.y));
    ex.z = __expf(lrelu(av.z + dv.z));
    ex.w = __expf(lrelu(av.w + dv.w));
    red_add_v4(g_den1 + d * H1, ex);
}

// ---------------------------------------------------------------------------
// Layer1 aggregation: 1 warp / edge. Lane l covers features [4l,4l+3]
// (head = l>>3 constant within the float4). 32 x red.v4 per edge.
// ---------------------------------------------------------------------------
__global__ void edge_agg1_kernel(const void* __restrict__ ei, int E, int etot) {
    int gtid = blockIdx.x * blockDim.x + threadIdx.x;
    int e = gtid >> 5;
    int lane = gtid & 31;
    if (e >= etot) return;
    int s, d;
    load_edge(ei, e, E, s, d);
    int h = lane >> 3;
    float ev = g_as1[s * H1 + h] + g_ad1[d * H1 + h];
    float alpha = __expf(lrelu(ev)) / g_den1[d * H1 + h];
    float4 hv = ((const float4*)g_h1)[(long long)s * 32 + lane];
    hv.x *= alpha; hv.y *= alpha; hv.z *= alpha; hv.w *= alpha;
    red_add_v4(g_x1 + (long long)d * C1 + lane * 4, hv);
}

// ---------------------------------------------------------------------------
// finish: add bias + ELU in place.
// ---------------------------------------------------------------------------
__global__ void finish1_kernel(const float* __restrict__ b1, int Nn) {
    long long i = (long long)blockIdx.x * blockDim.x + threadIdx.x;
    if (i >= (long long)Nn * C1) return;
    float v = g_x1[i] + b1[(int)(i & (C1 - 1))];
    g_x1[i] = v > 0.f ? v : expm1f(v);
}

__global__ void finish2_kernel(const float* __restrict__ b2, int Nn) {
    long long i = (long long)blockIdx.x * blockDim.x + threadIdx.x;
    if (i >= (long long)Nn * HID) return;
    float v = g_o2[i] + b2[(int)(i & (HID - 1))];
    g_o2[i] = v > 0.f ? v : expm1f(v);
}

// ---------------------------------------------------------------------------
// GEMM2: h2 = elu(out1) @ W2 ([N,128]x[128,32]) fused with a_s/a_d.
// 1 warp handles 4 nodes; lane = output column.
// ---------------------------------------------------------------------------
__global__ __launch_bounds__(256) void gemm2_kernel(
    const float* __restrict__ W2, const float* __restrict__ a2s,
    const float* __restrict__ a2d, int Nn) {
    int warp = (blockIdx.x * blockDim.x + threadIdx.x) >> 5;
    int lane = threadIdx.x & 31;
    int n0 = warp * 4;
    if (n0 >= Nn) return;
    float acc[4] = {0.f, 0.f, 0.f, 0.f};
    for (int k0 = 0; k0 < C1; k0 += 32) {
        float xk[4];
#pragma unroll
        for (int m = 0; m < 4; m++) {
            int n = n0 + m;
            xk[m] = (n < Nn) ? g_x1[(long long)n * C1 + k0 + lane] : 0.f;
        }
#pragma unroll
        for (int j = 0; j < 32; j++) {
            float wv = W2[(k0 + j) * HID + lane];
#pragma unroll
            for (int m = 0; m < 4; m++)
                acc[m] += __shfl_sync(0xffffffffu, xk[m], j) * wv;
        }
    }
    float asv = a2s[lane], adv = a2d[lane];
#pragma unroll
    for (int m = 0; m < 4; m++) {
        int n = n0 + m;
        if (n < Nn) g_h2[(long long)n * HID + lane] = acc[m];
        float s = acc[m] * asv;
        float d = acc[m] * adv;
#pragma unroll
        for (int off = 16; off; off >>= 1) {
            s += __shfl_down_sync(0xffffffffu, s, off);
            d += __shfl_down_sync(0xffffffffu, d, off);
        }
        if (lane == 0 && n < Nn) { g_as2[n] = s; g_ad2[n] = d; }
    }
}

// ---------------------------------------------------------------------------
// Layer2 denominators + aggregation (1 head, 32 features).
// ---------------------------------------------------------------------------
__global__ void edge_den2_kernel(const void* __restrict__ ei, int E, int etot) {
    int i = blockIdx.x * blockDim.x + threadIdx.x;
    if (i >= etot) return;
    int s, d;
    load_edge(ei, i, E, s, d);
    float ev = lrelu(g_as2[s] + g_ad2[d]);
    atomicAdd(&g_den2[d], __expf(ev));
}

__global__ void edge_agg2_kernel(const void* __restrict__ ei, int E, int etot) {
    int gtid = blockIdx.x * blockDim.x + threadIdx.x;
    int e = gtid >> 3;          // 8 lanes per edge (32 feats = 8 x float4)
    int g = gtid & 7;
    if (e >= etot) return;
    int s, d;
    load_edge(ei, e, E, s, d);
    float ev = g_as2[s] + g_ad2[d];
    float alpha = __expf(lrelu(ev)) / g_den2[d];
    float4 hv = ((const float4*)g_h2)[(long long)s * 8 + g];
    hv.x *= alpha; hv.y *= alpha; hv.z *= alpha; hv.w *= alpha;
    red_add_v4(g_o2 + (long long)d * HID + g * 4, hv);
}

// ---------------------------------------------------------------------------
// Actor/critic heads: logits[a,n] = h2f[n,:] . Wa[:,a] + ba[a] (transposed
// coalesced write via smem tile); value = bc + mean_n(h2f[n,:] . Wc).
// Block = 1024 threads = 32 warps = 32 nodes.
// ---------------------------------------------------------------------------
__global__ __launch_bounds__(1024) void heads_kernel(
    const float* __restrict__ Wa, const float* __restrict__ ba,
    const float* __restrict__ Wc, const float* __restrict__ bc,
    float* __restrict__ out, int Nn) {
    __shared__ float Was[AGENTS * HID];
    __shared__ float tile[32][33];
    __shared__ float warr[32];
    int t = threadIdx.x;
    Was[t & (AGENTS * HID - 1)] = Wa[t & (AGENTS * HID - 1)];
    __syncthreads();

    int w = t >> 5, lane = t & 31;
    int n = blockIdx.x * 32 + w;
    float hv = (n < Nn) ? g_o2[(long long)n * HID + lane] : 0.f;

    float acc = 0.f;
    float vs = hv * Wc[lane];
#pragma unroll
    for (int f = 0; f < HID; f++) {
        float xv = __shfl_sync(0xffffffffu, hv, f);
        acc += xv * Was[f * AGENTS + lane];
    }
    tile[w][lane] = acc + ba[lane];
#pragma unroll
    for (int off = 16; off; off >>= 1) vs += __shfl_down_sync(0xffffffffu, vs, off);
    if (lane == 0) warr[w] = vs;
    __syncthreads();

    // coalesced transposed write: warp w = agent row w, lane = node in block
    int n2 = blockIdx.x * 32 + lane;
    if (n2 < Nn) out[(long long)w * Nn + n2] = tile[lane][w];

    if (t == 0) {
        float bs = 0.f;
#pragma unroll
        for (int i = 0; i < 32; i++) bs += warr[i];
        atomicAdd(out + (long long)AGENTS * Nn, bs / (float)Nn);
        if (blockIdx.x == 0) atomicAdd(out + (long long)AGENTS * Nn, bc[0]);
    }
}

// ---------------------------------------------------------------------------
// Launch
// ---------------------------------------------------------------------------
extern "C" void kernel_launch(void* const* d_in, const int* in_sizes, int n_in,
                              void* d_out, int out_size) {
    const float* x   = (const float*)d_in[0];
    const void*  ei  = d_in[1];
    const float* W1  = (const float*)d_in[2];
    const float* a1s = (const float*)d_in[3];
    const float* a1d = (const float*)d_in[4];
    const float* b1  = (const float*)d_in[5];
    const float* W2  = (const float*)d_in[6];
    const float* a2s = (const float*)d_in[7];
    const float* a2d = (const float*)d_in[8];
    const float* b2  = (const float*)d_in[9];
    const float* Wa  = (const float*)d_in[10];
    const float* ba  = (const float*)d_in[11];
    const float* Wc  = (const float*)d_in[12];
    const float* bc  = (const float*)d_in[13];
    float* out = (float*)d_out;

    int Nn   = in_sizes[0] / INDIM;   // 50000
    int E    = in_sizes[1] / 2;       // 800000
    int etot = E + Nn;                // 850000 (with self-loops)

    detect_i64_kernel<<<1, 1>>>((const unsigned int*)ei);
    zero_scratch_kernel<<<2048, 256>>>(out, Nn);

    // ---- layer 1 ----
    gemm1_kernel<<<(Nn + 15) / 16, 128>>>(x, W1, a1s, a1d, Nn);
    edge_den1_kernel<<<(etot + 255) / 256, 256>>>(ei, E, etot);
    {
        long long th = (long long)etot * 32;
        edge_agg1_kernel<<<(unsigned)((th + 255) / 256), 256>>>(ei, E, etot);
    }
    {
        long long th = (long long)Nn * C1;
        finish1_kernel<<<(unsigned)((th + 255) / 256), 256>>>(b1, Nn);
    }

    // ---- layer 2 ----
    gemm2_kernel<<<(Nn + 31) / 32, 256>>>(W2, a2s, a2d, Nn);
    edge_den2_kernel<<<(etot + 255) / 256, 256>>>(ei, E, etot);
    {
        long long th = (long long)etot * 8;
        edge_agg2_kernel<<<(unsigned)((th + 255) / 256), 256>>>(ei, E, etot);
    }
    {
        long long th = (long long)Nn * HID;
        finish2_kernel<<<(unsigned)((th + 255) / 256), 256>>>(b2, Nn);
    }

    // ---- heads ----
    heads_kernel<<<(Nn + 31) / 32, 1024>>>(Wa, ba, Wc, bc, out, Nn);
}

// round 5
// speedup vs baseline: 1.0686x; 1.0686x over previous
#include <cuda_runtime.h>
#include <math.h>

// ---------------------------------------------------------------------------
// Problem constants
// ---------------------------------------------------------------------------
#define MAXN   50000
#define MAXE   1048576      // E + N self-loops (850000 actual)
#define INDIM  128
#define HID    32
#define H1     4
#define C1     128          // H1*HID
#define AGENTS 32
#define NEG    0.2f

// ---------------------------------------------------------------------------
// Device scratch (allocations forbidden)
// ---------------------------------------------------------------------------
__device__ __align__(16) float g_h1 [MAXN * C1];   // layer1 pre-attention feats
__device__ __align__(16) float g_x1 [MAXN * C1];   // layer1 out (biased+elu)
__device__ __align__(16) float g_as1[MAXN * H1];
__device__ __align__(16) float g_ad1[MAXN * H1];
__device__ __align__(16) float g_h2 [MAXN * HID];
__device__ __align__(16) float g_o2 [MAXN * HID];  // layer2 out (biased+elu)
__device__ float g_as2[MAXN];
__device__ float g_ad2[MAXN];
__device__ int   g_cnt[MAXN];
__device__ int   g_rowstart[MAXN + 1];
__device__ int   g_rowcur[MAXN];
__device__ int   g_csr[MAXE];          // src node per bucketed edge
__device__ int   g_is64;

// ---------------------------------------------------------------------------
// Helpers
// ---------------------------------------------------------------------------
__device__ __forceinline__ float lrelu(float v) { return v > 0.f ? v : NEG * v; }
__device__ __forceinline__ float elu(float v)   { return v > 0.f ? v : expm1f(v); }

__device__ __forceinline__ int load_dst(const void* __restrict__ ei, int i, int E) {
    if (i >= E) return i - E;
    return g_is64 ? (int)((const long long*)ei)[E + i] : ((const int*)ei)[E + i];
}
__device__ __forceinline__ int load_src(const void* __restrict__ ei, int i, int E) {
    if (i >= E) return i - E;
    return g_is64 ? (int)((const long long*)ei)[i] : ((const int*)ei)[i];
}

// ---------------------------------------------------------------------------
// zero counts + value cell + dtype probe (int64 -> odd 32-bit words all zero)
// ---------------------------------------------------------------------------
__global__ void prep_kernel(const unsigned int* __restrict__ w,
                            float* __restrict__ out, int Nn) {
    int i = blockIdx.x * blockDim.x + threadIdx.x;
    if (i < Nn) g_cnt[i] = 0;
    if (i == 0) {
        out[(long long)AGENTS * Nn] = 0.f;
        int allz = 1;
        for (int k = 0; k < 16; k++)
            if (w[2 * k + 1] != 0u) allz = 0;
        g_is64 = allz;
    }
}

// ---------------------------------------------------------------------------
// CSR build: histogram -> scan -> scatter
// ---------------------------------------------------------------------------
__global__ void count_kernel(const void* __restrict__ ei, int E, int etot) {
    int i = blockIdx.x * blockDim.x + threadIdx.x;
    if (i >= etot) return;
    atomicAdd(&g_cnt[load_dst(ei, i, E)], 1);
}

__global__ __launch_bounds__(1024) void scan_kernel(int Nn, int etot) {
    __shared__ int wsum[32];
    int t = threadIdx.x;
    const int PER = (MAXN + 1023) / 1024;       // 49
    int lo = t * PER, hi = min(lo + PER, Nn);
    int sum = 0;
    for (int i = lo; i < hi; i++) sum += g_cnt[i];

    int lane = t & 31, w = t >> 5;
    int v = sum;
#pragma unroll
    for (int off = 1; off < 32; off <<= 1) {
        int u = __shfl_up_sync(0xffffffffu, v, off);
        if (lane >= off) v += u;
    }
    if (lane == 31) wsum[w] = v;
    __syncthreads();
    if (w == 0) {
        int u = wsum[lane];
#pragma unroll
        for (int off = 1; off < 32; off <<= 1) {
            int p = __shfl_up_sync(0xffffffffu, u, off);
            if (lane >= off) u += p;
        }
        wsum[lane] = u;
    }
    __syncthreads();
    int base = (w > 0 ? wsum[w - 1] : 0) + (v - sum);   // exclusive prefix
    int run = base;
    for (int i = lo; i < hi; i++) {
        g_rowstart[i] = run;
        g_rowcur[i]   = run;
        run += g_cnt[i];
    }
    if (t == 1023) g_rowstart[Nn] = etot;
}

__global__ void scatter_kernel(const void* __restrict__ ei, int E, int etot) {
    int i = blockIdx.x * blockDim.x + threadIdx.x;
    if (i >= etot) return;
    int d = load_dst(ei, i, E);
    int s = load_src(ei, i, E);
    int pos = atomicAdd(&g_rowcur[d], 1);
    g_csr[pos] = s;
}

// ---------------------------------------------------------------------------
// GEMM1: h1 = x @ W1 ([N,128]x[128,128]) fused with a_s/a_d reductions.
// ---------------------------------------------------------------------------
__global__ __launch_bounds__(128) void gemm1_kernel(
    const float* __restrict__ x, const float* __restrict__ W1,
    const float* __restrict__ a1s, const float* __restrict__ a1d, int Nn) {
    __shared__ float xs[16][INDIM];
    int t  = threadIdx.x;
    int n0 = blockIdx.x * 16;

    const float4* xv = (const float4*)x;
    for (int i = t; i < 16 * 32; i += 128) {
        int m = i >> 5, c = i & 31;
        int n = n0 + m;
        float4 v = (n < Nn) ? xv[(long long)n * 32 + c] : make_float4(0.f, 0.f, 0.f, 0.f);
        ((float4*)(&xs[0][0]))[m * 32 + c] = v;
    }
    __syncthreads();

    float acc[16];
#pragma unroll
    for (int m = 0; m < 16; m++) acc[m] = 0.f;

    for (int kt = 0; kt < INDIM; kt += 16) {
        float w[16];
#pragma unroll
        for (int j = 0; j < 16; j++) w[j] = W1[(kt + j) * C1 + t];
#pragma unroll
        for (int m = 0; m < 16; m++) {
            const float4* xr = (const float4*)&xs[m][kt];
            float4 x0 = xr[0], x1 = xr[1], x2 = xr[2], x3 = xr[3];
            acc[m] += x0.x * w[0]  + x0.y * w[1]  + x0.z * w[2]  + x0.w * w[3]
                    + x1.x * w[4]  + x1.y * w[5]  + x1.z * w[6]  + x1.w * w[7]
                    + x2.x * w[8]  + x2.y * w[9]  + x2.z * w[10] + x2.w * w[11]
                    + x3.x * w[12] + x3.y * w[13] + x3.z * w[14] + x3.w * w[15];
        }
    }

    float asv = a1s[t], adv = a1d[t];
    int lane = t & 31;
    int head = t >> 5;
#pragma unroll
    for (int m = 0; m < 16; m++) {
        int n = n0 + m;
        if (n < Nn) g_h1[(long long)n * C1 + t] = acc[m];
        float s = acc[m] * asv;
        float d = acc[m] * adv;
#pragma unroll
        for (int off = 16; off; off >>= 1) {
            s += __shfl_down_sync(0xffffffffu, s, off);
            d += __shfl_down_sync(0xffffffffu, d, off);
        }
        if (lane == 0 && n < Nn) {
            g_as1[n * H1 + head] = s;
            g_ad1[n * H1 + head] = d;
        }
    }
}

// ---------------------------------------------------------------------------
// Layer1 attention, gather-side, atomic-free. 1 warp / destination node.
// Phase 1: edge-parallel softmax denominator (4 heads, in registers).
// Phase 2: feature-parallel weighted gather; fused bias+ELU epilogue.
// ---------------------------------------------------------------------------
__global__ __launch_bounds__(256) void attn1_kernel(
    const float* __restrict__ b1, int Nn) {
    int warp = (blockIdx.x * blockDim.x + threadIdx.x) >> 5;
    int lane = threadIdx.x & 31;
    if (warp >= Nn) return;
    int n = warp;
    int start = g_rowstart[n], end = g_rowstart[n + 1];
    float4 adv = *(const float4*)(g_ad1 + n * H1);

    // ---- phase 1: denominators ----
    float dx = 0.f, dy = 0.f, dz = 0.f, dw = 0.f;
    for (int i = start + lane; i < end; i += 32) {
        int s = g_csr[i];
        float4 av = *(const float4*)(g_as1 + s * H1);
        dx += __expf(lrelu(av.x + adv.x));
        dy += __expf(lrelu(av.y + adv.y));
        dz += __expf(lrelu(av.z + adv.z));
        dw += __expf(lrelu(av.w + adv.w));
    }
#pragma unroll
    for (int off = 16; off; off >>= 1) {
        dx += __shfl_xor_sync(0xffffffffu, dx, off);
        dy += __shfl_xor_sync(0xffffffffu, dy, off);
        dz += __shfl_xor_sync(0xffffffffu, dz, off);
        dw += __shfl_xor_sync(0xffffffffu, dw, off);
    }
    int h = lane >> 3;  // head for this lane's float4
    float denh = (h == 0) ? dx : (h == 1) ? dy : (h == 2) ? dz : dw;
    float adh  = (h == 0) ? adv.x : (h == 1) ? adv.y : (h == 2) ? adv.z : adv.w;
    float rden = 1.f / denh;

    // ---- phase 2: weighted aggregation (unroll x2 for MLP) ----
    float ax = 0.f, ay = 0.f, az = 0.f, aw = 0.f;
    int i = start;
    for (; i + 1 < end; i += 2) {
        int s0 = g_csr[i], s1 = g_csr[i + 1];
        float e0 = g_as1[s0 * H1 + h] + adh;
        float e1 = g_as1[s1 * H1 + h] + adh;
        float4 v0 = ((const float4*)g_h1)[(long long)s0 * 32 + lane];
        float4 v1 = ((const float4*)g_h1)[(long long)s1 * 32 + lane];
        float al0 = __expf(lrelu(e0)) * rden;
        float al1 = __expf(lrelu(e1)) * rden;
        ax += al0 * v0.x + al1 * v1.x;
        ay += al0 * v0.y + al1 * v1.y;
        az += al0 * v0.z + al1 * v1.z;
        aw += al0 * v0.w + al1 * v1.w;
    }
    if (i < end) {
        int s0 = g_csr[i];
        float e0 = g_as1[s0 * H1 + h] + adh;
        float4 v0 = ((const float4*)g_h1)[(long long)s0 * 32 + lane];
        float al0 = __expf(lrelu(e0)) * rden;
        ax += al0 * v0.x; ay += al0 * v0.y; az += al0 * v0.z; aw += al0 * v0.w;
    }

    float4 bb = ((const float4*)b1)[lane];
    float4 o;
    o.x = elu(ax + bb.x); o.y = elu(ay + bb.y);
    o.z = elu(az + bb.z); o.w = elu(aw + bb.w);
    ((float4*)g_x1)[(long long)n * 32 + lane] = o;
}

// ---------------------------------------------------------------------------
// GEMM2: h2 = x1 @ W2 ([N,128]x[128,32]) fused with a_s/a_d.
// ---------------------------------------------------------------------------
__global__ __launch_bounds__(256) void gemm2_kernel(
    const float* __restrict__ W2, const float* __restrict__ a2s,
    const float* __restrict__ a2d, int Nn) {
    int warp = (blockIdx.x * blockDim.x + threadIdx.x) >> 5;
    int lane = threadIdx.x & 31;
    int n0 = warp * 4;
    if (n0 >= Nn) return;
    float acc[4] = {0.f, 0.f, 0.f, 0.f};
    for (int k0 = 0; k0 < C1; k0 += 32) {
        float xk[4];
#pragma unroll
        for (int m = 0; m < 4; m++) {
            int n = n0 + m;
            xk[m] = (n < Nn) ? g_x1[(long long)n * C1 + k0 + lane] : 0.f;
        }
#pragma unroll
        for (int j = 0; j < 32; j++) {
            float wv = W2[(k0 + j) * HID + lane];
#pragma unroll
            for (int m = 0; m < 4; m++)
                acc[m] += __shfl_sync(0xffffffffu, xk[m], j) * wv;
        }
    }
    float asv = a2s[lane], adv = a2d[lane];
#pragma unroll
    for (int m = 0; m < 4; m++) {
        int n = n0 + m;
        if (n < Nn) g_h2[(long long)n * HID + lane] = acc[m];
        float s = acc[m] * asv;
        float d = acc[m] * adv;
#pragma unroll
        for (int off = 16; off; off >>= 1) {
            s += __shfl_down_sync(0xffffffffu, s, off);
            d += __shfl_down_sync(0xffffffffu, d, off);
        }
        if (lane == 0 && n < Nn) { g_as2[n] = s; g_ad2[n] = d; }
    }
}

// ---------------------------------------------------------------------------
// Layer2 attention, gather-side, 1 warp / node, lane = feature.
// ---------------------------------------------------------------------------
__global__ __launch_bounds__(256) void attn2_kernel(
    const float* __restrict__ b2, int Nn) {
    int warp = (blockIdx.x * blockDim.x + threadIdx.x) >> 5;
    int lane = threadIdx.x & 31;
    if (warp >= Nn) return;
    int n = warp;
    int start = g_rowstart[n], end = g_rowstart[n + 1];
    float adn = g_ad2[n];

    float den = 0.f;
    for (int i = start + lane; i < end; i += 32)
        den += __expf(lrelu(g_as2[g_csr[i]] + adn));
#pragma unroll
    for (int off = 16; off; off >>= 1)
        den += __shfl_xor_sync(0xffffffffu, den, off);
    float rden = 1.f / den;

    float acc = 0.f;
    int i = start;
    for (; i + 1 < end; i += 2) {
        int s0 = g_csr[i], s1 = g_csr[i + 1];
        float al0 = __expf(lrelu(g_as2[s0] + adn)) * rden;
        float al1 = __expf(lrelu(g_as2[s1] + adn)) * rden;
        float v0 = g_h2[(long long)s0 * HID + lane];
        float v1 = g_h2[(long long)s1 * HID + lane];
        acc += al0 * v0 + al1 * v1;
    }
    if (i < end) {
        int s0 = g_csr[i];
        acc += __expf(lrelu(g_as2[s0] + adn)) * rden * g_h2[(long long)s0 * HID + lane];
    }
    g_o2[(long long)n * HID + lane] = elu(acc + b2[lane]);
}

// ---------------------------------------------------------------------------
// Actor/critic heads. Block = 32 warps = 32 nodes, smem transpose for
// coalesced [AGENTS, N] writes; block-level value partial into out[A*N].
// ---------------------------------------------------------------------------
__global__ __launch_bounds__(1024) void heads_kernel(
    const float* __restrict__ Wa, const float* __restrict__ ba,
    const float* __restrict__ Wc, const float* __restrict__ bc,
    float* __restrict__ out, int Nn) {
    __shared__ float Was[AGENTS * HID];
    __shared__ float tile[32][33];
    __shared__ float warr[32];
    int t = threadIdx.x;
    Was[t & (AGENTS * HID - 1)] = Wa[t & (AGENTS * HID - 1)];
    __syncthreads();

    int w = t >> 5, lane = t & 31;
    int n = blockIdx.x * 32 + w;
    float hv = (n < Nn) ? g_o2[(long long)n * HID + lane] : 0.f;

    float acc = 0.f;
    float vs = hv * Wc[lane];
#pragma unroll
    for (int f = 0; f < HID; f++) {
        float xv = __shfl_sync(0xffffffffu, hv, f);
        acc += xv * Was[f * AGENTS + lane];
    }
    tile[w][lane] = acc + ba[lane];
#pragma unroll
    for (int off = 16; off; off >>= 1) vs += __shfl_down_sync(0xffffffffu, vs, off);
    if (lane == 0) warr[w] = vs;
    __syncthreads();

    int n2 = blockIdx.x * 32 + lane;
    if (n2 < Nn) out[(long long)w * Nn + n2] = tile[lane][w];

    if (t == 0) {
        float bs = 0.f;
#pragma unroll
        for (int i = 0; i < 32; i++) bs += warr[i];
        atomicAdd(out + (long long)AGENTS * Nn, bs / (float)Nn);
        if (blockIdx.x == 0) atomicAdd(out + (long long)AGENTS * Nn, bc[0]);
    }
}

// ---------------------------------------------------------------------------
// Launch
// ---------------------------------------------------------------------------
extern "C" void kernel_launch(void* const* d_in, const int* in_sizes, int n_in,
                              void* d_out, int out_size) {
    const float* x   = (const float*)d_in[0];
    const void*  ei  = d_in[1];
    const float* W1  = (const float*)d_in[2];
    const float* a1s = (const float*)d_in[3];
    const float* a1d = (const float*)d_in[4];
    const float* b1  = (const float*)d_in[5];
    const float* W2  = (const float*)d_in[6];
    const float* a2s = (const float*)d_in[7];
    const float* a2d = (const float*)d_in[8];
    const float* b2  = (const float*)d_in[9];
    const float* Wa  = (const float*)d_in[10];
    const float* ba  = (const float*)d_in[11];
    const float* Wc  = (const float*)d_in[12];
    const float* bc  = (const float*)d_in[13];
    float* out = (float*)d_out;

    int Nn   = in_sizes[0] / INDIM;   // 50000
    int E    = in_sizes[1] / 2;       // 800000
    int etot = E + Nn;

    // CSR build (overlappable with gemm1 conceptually; same stream = serial)
    prep_kernel<<<(Nn + 255) / 256, 256>>>((const unsigned int*)ei, out, Nn);
    count_kernel<<<(etot + 255) / 256, 256>>>(ei, E, etot);
    scan_kernel<<<1, 1024>>>(Nn, etot);
    scatter_kernel<<<(etot + 255) / 256, 256>>>(ei, E, etot);

    // layer 1
    gemm1_kernel<<<(Nn + 15) / 16, 128>>>(x, W1, a1s, a1d, Nn);
    {
        long long th = (long long)Nn * 32;
        attn1_kernel<<<(unsigned)((th + 255) / 256), 256>>>(b1, Nn);
    }

    // layer 2
    gemm2_kernel<<<(Nn + 31) / 32, 256>>>(W2, a2s, a2d, Nn);
    {
        long long th = (long long)Nn * 32;
        attn2_kernel<<<(unsigned)((th + 255) / 256), 256>>>(b2, Nn);
    }

    // heads
    heads_kernel<<<(Nn + 31) / 32, 1024>>>(Wa, ba, Wc, bc, out, Nn);
}

// round 6
// speedup vs baseline: 1.1154x; 1.0438x over previous
#include <cuda_runtime.h>
#include <cuda_fp16.h>
#include <math.h>

// ---------------------------------------------------------------------------
// Problem constants
// ---------------------------------------------------------------------------
#define MAXN   50000
#define MAXE   1048576
#define INDIM  128
#define HID    32
#define H1     4
#define C1     128
#define AGENTS 32
#define NEG    0.2f

// ---------------------------------------------------------------------------
// Device scratch
// ---------------------------------------------------------------------------
__device__ __align__(16) __half g_h1h[MAXN * C1];  // layer1 feats (fp16)
__device__ __align__(16) float g_x1 [MAXN * C1];   // layer1 out (biased+elu)
__device__ __align__(16) float g_as1[MAXN * H1];
__device__ __align__(16) float g_ad1[MAXN * H1];
__device__ __align__(16) float g_h2 [MAXN * HID];
__device__ __align__(16) float g_o2 [MAXN * HID];
__device__ float g_as2[MAXN];
__device__ float g_ad2[MAXN];
__device__ int   g_cnt[MAXN];
__device__ int   g_rowstart[MAXN + 1];
__device__ int   g_rowcur[MAXN];
__device__ int   g_csr[MAXE];
__device__ int   g_is64;

// ---------------------------------------------------------------------------
// Helpers
// ---------------------------------------------------------------------------
__device__ __forceinline__ float lrelu(float v) { return v > 0.f ? v : NEG * v; }
__device__ __forceinline__ float elu(float v)   { return v > 0.f ? v : expm1f(v); }

__device__ __forceinline__ int load_dst(const void* __restrict__ ei, int i, int E) {
    if (i >= E) return i - E;
    return g_is64 ? (int)((const long long*)ei)[E + i] : ((const int*)ei)[E + i];
}
__device__ __forceinline__ int load_src(const void* __restrict__ ei, int i, int E) {
    if (i >= E) return i - E;
    return g_is64 ? (int)((const long long*)ei)[i] : ((const int*)ei)[i];
}

// ---------------------------------------------------------------------------
// prep: zero counts + value cell + int64 probe
// ---------------------------------------------------------------------------
__global__ void prep_kernel(const unsigned int* __restrict__ w,
                            float* __restrict__ out, int Nn) {
    int i = blockIdx.x * blockDim.x + threadIdx.x;
    if (i < Nn) g_cnt[i] = 0;
    if (i == 0) {
        out[(long long)AGENTS * Nn] = 0.f;
        int allz = 1;
        for (int k = 0; k < 16; k++)
            if (w[2 * k + 1] != 0u) allz = 0;
        g_is64 = allz;
    }
}

// ---------------------------------------------------------------------------
// CSR build: histogram (4 edges/thread) -> scan -> scatter (4 edges/thread)
// ---------------------------------------------------------------------------
__global__ void count_kernel(const void* __restrict__ ei, int E, int etot) {
    int i0 = (blockIdx.x * blockDim.x + threadIdx.x) * 4;
#pragma unroll
    for (int k = 0; k < 4; k++) {
        int i = i0 + k;
        if (i < etot) atomicAdd(&g_cnt[load_dst(ei, i, E)], 1);
    }
}

__global__ __launch_bounds__(1024) void scan_kernel(int Nn, int etot) {
    __shared__ int wsum[32];
    int t = threadIdx.x;
    const int PER = (MAXN + 1023) / 1024;
    int lo = t * PER, hi = min(lo + PER, Nn);
    int sum = 0;
    for (int i = lo; i < hi; i++) sum += g_cnt[i];

    int lane = t & 31, w = t >> 5;
    int v = sum;
#pragma unroll
    for (int off = 1; off < 32; off <<= 1) {
        int u = __shfl_up_sync(0xffffffffu, v, off);
        if (lane >= off) v += u;
    }
    if (lane == 31) wsum[w] = v;
    __syncthreads();
    if (w == 0) {
        int u = wsum[lane];
#pragma unroll
        for (int off = 1; off < 32; off <<= 1) {
            int p = __shfl_up_sync(0xffffffffu, u, off);
            if (lane >= off) u += p;
        }
        wsum[lane] = u;
    }
    __syncthreads();
    int base = (w > 0 ? wsum[w - 1] : 0) + (v - sum);
    int run = base;
    for (int i = lo; i < hi; i++) {
        g_rowstart[i] = run;
        g_rowcur[i]   = run;
        run += g_cnt[i];
    }
    if (t == 1023) g_rowstart[Nn] = etot;
}

__global__ void scatter_kernel(const void* __restrict__ ei, int E, int etot) {
    int i0 = (blockIdx.x * blockDim.x + threadIdx.x) * 4;
#pragma unroll
    for (int k = 0; k < 4; k++) {
        int i = i0 + k;
        if (i < etot) {
            int d = load_dst(ei, i, E);
            int s = load_src(ei, i, E);
            int pos = atomicAdd(&g_rowcur[d], 1);
            g_csr[pos] = s;
        }
    }
}

// ---------------------------------------------------------------------------
// GEMM1: h1 = x @ W1 ([N,128]x[128,128]) fused a_s/a_d; h1 stored fp16.
// ---------------------------------------------------------------------------
__global__ __launch_bounds__(128) void gemm1_kernel(
    const float* __restrict__ x, const float* __restrict__ W1,
    const float* __restrict__ a1s, const float* __restrict__ a1d, int Nn) {
    __shared__ float xs[16][INDIM];
    int t  = threadIdx.x;
    int n0 = blockIdx.x * 16;

    const float4* xv = (const float4*)x;
    for (int i = t; i < 16 * 32; i += 128) {
        int m = i >> 5, c = i & 31;
        int n = n0 + m;
        float4 v = (n < Nn) ? xv[(long long)n * 32 + c] : make_float4(0.f, 0.f, 0.f, 0.f);
        ((float4*)(&xs[0][0]))[m * 32 + c] = v;
    }
    __syncthreads();

    float acc[16];
#pragma unroll
    for (int m = 0; m < 16; m++) acc[m] = 0.f;

    for (int kt = 0; kt < INDIM; kt += 16) {
        float w[16];
#pragma unroll
        for (int j = 0; j < 16; j++) w[j] = W1[(kt + j) * C1 + t];
#pragma unroll
        for (int m = 0; m < 16; m++) {
            const float4* xr = (const float4*)&xs[m][kt];
            float4 x0 = xr[0], x1 = xr[1], x2 = xr[2], x3 = xr[3];
            acc[m] += x0.x * w[0]  + x0.y * w[1]  + x0.z * w[2]  + x0.w * w[3]
                    + x1.x * w[4]  + x1.y * w[5]  + x1.z * w[6]  + x1.w * w[7]
                    + x2.x * w[8]  + x2.y * w[9]  + x2.z * w[10] + x2.w * w[11]
                    + x3.x * w[12] + x3.y * w[13] + x3.z * w[14] + x3.w * w[15];
        }
    }

    float asv = a1s[t], adv = a1d[t];
    int lane = t & 31;
    int head = t >> 5;
#pragma unroll
    for (int m = 0; m < 16; m++) {
        int n = n0 + m;
        if (n < Nn) g_h1h[(long long)n * C1 + t] = __float2half_rn(acc[m]);
        float s = acc[m] * asv;
        float d = acc[m] * adv;
#pragma unroll
        for (int off = 16; off; off >>= 1) {
            s += __shfl_down_sync(0xffffffffu, s, off);
            d += __shfl_down_sync(0xffffffffu, d, off);
        }
        if (lane == 0 && n < Nn) {
            g_as1[n * H1 + head] = s;
            g_ad1[n * H1 + head] = d;
        }
    }
}

// ---------------------------------------------------------------------------
// Layer1 attention, SINGLE PASS, gather-side, warp/node.
// Chunk of 32 edges: lane computes numerator (4 heads) -> smem stage ->
// inner loop (x2 unrolled) accumulates num*h1 and den; divide at the end.
// ---------------------------------------------------------------------------
__global__ __launch_bounds__(256) void attn1_kernel(
    const float* __restrict__ b1, int Nn) {
    __shared__ float4 s_num[8][32];
    __shared__ int    s_src[8][32];
    int wg   = threadIdx.x >> 5;
    int warp = (blockIdx.x * blockDim.x + threadIdx.x) >> 5;
    int lane = threadIdx.x & 31;
    if (warp >= Nn) return;
    int start = g_rowstart[warp], end = g_rowstart[warp + 1];
    float4 adv = *(const float4*)(g_ad1 + warp * H1);
    int h = lane >> 3;

    float4 den = make_float4(0.f, 0.f, 0.f, 0.f);
    float ax = 0.f, ay = 0.f, az = 0.f, aw = 0.f;
    const uint2* h1 = (const uint2*)g_h1h;   // 4 halfs per uint2, 32 per row

    for (int base = start; base < end; base += 32) {
        int cnt = min(32, end - base);
        int s = 0;
        float4 nm = make_float4(0.f, 0.f, 0.f, 0.f);
        if (lane < cnt) {
            s = g_csr[base + lane];
            float4 av = *(const float4*)(g_as1 + s * H1);
            nm.x = __expf(lrelu(av.x + adv.x));
            nm.y = __expf(lrelu(av.y + adv.y));
            nm.z = __expf(lrelu(av.z + adv.z));
            nm.w = __expf(lrelu(av.w + adv.w));
            den.x += nm.x; den.y += nm.y; den.z += nm.z; den.w += nm.w;
        }
        s_num[wg][lane] = nm;
        s_src[wg][lane] = s;
        __syncwarp();

        int j = 0;
        for (; j + 2 <= cnt; j += 2) {
            int sj0 = s_src[wg][j];
            int sj1 = s_src[wg][j + 1];
            float a0 = ((const float*)&s_num[wg][j])[h];
            float a1 = ((const float*)&s_num[wg][j + 1])[h];
            uint2 u0 = h1[(long long)sj0 * 32 + lane];
            uint2 u1 = h1[(long long)sj1 * 32 + lane];
            float2 f00 = __half22float2(*(const __half2*)&u0.x);
            float2 f01 = __half22float2(*(const __half2*)&u0.y);
            float2 f10 = __half22float2(*(const __half2*)&u1.x);
            float2 f11 = __half22float2(*(const __half2*)&u1.y);
            ax += a0 * f00.x + a1 * f10.x;
            ay += a0 * f00.y + a1 * f10.y;
            az += a0 * f01.x + a1 * f11.x;
            aw += a0 * f01.y + a1 * f11.y;
        }
        if (j < cnt) {
            int sj0 = s_src[wg][j];
            float a0 = ((const float*)&s_num[wg][j])[h];
            uint2 u0 = h1[(long long)sj0 * 32 + lane];
            float2 f00 = __half22float2(*(const __half2*)&u0.x);
            float2 f01 = __half22float2(*(const __half2*)&u0.y);
            ax += a0 * f00.x; ay += a0 * f00.y;
            az += a0 * f01.x; aw += a0 * f01.y;
        }
        __syncwarp();
    }

#pragma unroll
    for (int off = 16; off; off >>= 1) {
        den.x += __shfl_xor_sync(0xffffffffu, den.x, off);
        den.y += __shfl_xor_sync(0xffffffffu, den.y, off);
        den.z += __shfl_xor_sync(0xffffffffu, den.z, off);
        den.w += __shfl_xor_sync(0xffffffffu, den.w, off);
    }
    float dh = (h == 0) ? den.x : (h == 1) ? den.y : (h == 2) ? den.z : den.w;
    float rden = 1.f / dh;

    float4 bb = ((const float4*)b1)[lane];
    float4 o;
    o.x = elu(ax * rden + bb.x); o.y = elu(ay * rden + bb.y);
    o.z = elu(az * rden + bb.z); o.w = elu(aw * rden + bb.w);
    ((float4*)g_x1)[(long long)warp * 32 + lane] = o;
}

// ---------------------------------------------------------------------------
// GEMM2: h2 = x1 @ W2 ([N,128]x[128,32]) fused a_s/a_d.
// ---------------------------------------------------------------------------
__global__ __launch_bounds__(256) void gemm2_kernel(
    const float* __restrict__ W2, const float* __restrict__ a2s,
    const float* __restrict__ a2d, int Nn) {
    int warp = (blockIdx.x * blockDim.x + threadIdx.x) >> 5;
    int lane = threadIdx.x & 31;
    int n0 = warp * 4;
    if (n0 >= Nn) return;
    float acc[4] = {0.f, 0.f, 0.f, 0.f};
    for (int k0 = 0; k0 < C1; k0 += 32) {
        float xk[4];
#pragma unroll
        for (int m = 0; m < 4; m++) {
            int n = n0 + m;
            xk[m] = (n < Nn) ? g_x1[(long long)n * C1 + k0 + lane] : 0.f;
        }
#pragma unroll
        for (int j = 0; j < 32; j++) {
            float wv = W2[(k0 + j) * HID + lane];
#pragma unroll
            for (int m = 0; m < 4; m++)
                acc[m] += __shfl_sync(0xffffffffu, xk[m], j) * wv;
        }
    }
    float asv = a2s[lane], adv = a2d[lane];
#pragma unroll
    for (int m = 0; m < 4; m++) {
        int n = n0 + m;
        if (n < Nn) g_h2[(long long)n * HID + lane] = acc[m];
        float s = acc[m] * asv;
        float d = acc[m] * adv;
#pragma unroll
        for (int off = 16; off; off >>= 1) {
            s += __shfl_down_sync(0xffffffffu, s, off);
            d += __shfl_down_sync(0xffffffffu, d, off);
        }
        if (lane == 0 && n < Nn) { g_as2[n] = s; g_ad2[n] = d; }
    }
}

// ---------------------------------------------------------------------------
// Layer2 attention, SINGLE PASS, warp/node, lane = feature.
// ---------------------------------------------------------------------------
__global__ __launch_bounds__(256) void attn2_kernel(
    const float* __restrict__ b2, int Nn) {
    __shared__ float s_num[8][32];
    __shared__ int   s_src[8][32];
    int wg   = threadIdx.x >> 5;
    int warp = (blockIdx.x * blockDim.x + threadIdx.x) >> 5;
    int lane = threadIdx.x & 31;
    if (warp >= Nn) return;
    int start = g_rowstart[warp], end = g_rowstart[warp + 1];
    float adn = g_ad2[warp];

    float den = 0.f, acc = 0.f;
    for (int base = start; base < end; base += 32) {
        int cnt = min(32, end - base);
        int s = 0; float num = 0.f;
        if (lane < cnt) {
            s = g_csr[base + lane];
            num = __expf(lrelu(g_as2[s] + adn));
            den += num;
        }
        s_num[wg][lane] = num;
        s_src[wg][lane] = s;
        __syncwarp();

        int j = 0;
        for (; j + 2 <= cnt; j += 2) {
            int sj0 = s_src[wg][j], sj1 = s_src[wg][j + 1];
            float a0 = s_num[wg][j], a1 = s_num[wg][j + 1];
            float v0 = g_h2[(long long)sj0 * HID + lane];
            float v1 = g_h2[(long long)sj1 * HID + lane];
            acc += a0 * v0 + a1 * v1;
        }
        if (j < cnt) {
            int sj0 = s_src[wg][j];
            acc += s_num[wg][j] * g_h2[(long long)sj0 * HID + lane];
        }
        __syncwarp();
    }
#pragma unroll
    for (int off = 16; off; off >>= 1)
        den += __shfl_xor_sync(0xffffffffu, den, off);
    g_o2[(long long)warp * HID + lane] = elu(acc / den + b2[lane]);
}

// ---------------------------------------------------------------------------
// Actor/critic heads.
// ---------------------------------------------------------------------------
__global__ __launch_bounds__(1024) void heads_kernel(
    const float* __restrict__ Wa, const float* __restrict__ ba,
    const float* __restrict__ Wc, const float* __restrict__ bc,
    float* __restrict__ out, int Nn) {
    __shared__ float Was[AGENTS * HID];
    __shared__ float tile[32][33];
    __shared__ float warr[32];
    int t = threadIdx.x;
    Was[t & (AGENTS * HID - 1)] = Wa[t & (AGENTS * HID - 1)];
    __syncthreads();

    int w = t >> 5, lane = t & 31;
    int n = blockIdx.x * 32 + w;
    float hv = (n < Nn) ? g_o2[(long long)n * HID + lane] : 0.f;

    float acc = 0.f;
    float vs = hv * Wc[lane];
#pragma unroll
    for (int f = 0; f < HID; f++) {
        float xv = __shfl_sync(0xffffffffu, hv, f);
        acc += xv * Was[f * AGENTS + lane];
    }
    tile[w][lane] = acc + ba[lane];
#pragma unroll
    for (int off = 16; off; off >>= 1) vs += __shfl_down_sync(0xffffffffu, vs, off);
    if (lane == 0) warr[w] = vs;
    __syncthreads();

    int n2 = blockIdx.x * 32 + lane;
    if (n2 < Nn) out[(long long)w * Nn + n2] = tile[lane][w];

    if (t == 0) {
        float bs = 0.f;
#pragma unroll
        for (int i = 0; i < 32; i++) bs += warr[i];
        atomicAdd(out + (long long)AGENTS * Nn, bs / (float)Nn);
        if (blockIdx.x == 0) atomicAdd(out + (long long)AGENTS * Nn, bc[0]);
    }
}

// ---------------------------------------------------------------------------
// Launch (gemm1 placed 4th so ncu's fixed sample lands on it)
// ---------------------------------------------------------------------------
extern "C" void kernel_launch(void* const* d_in, const int* in_sizes, int n_in,
                              void* d_out, int out_size) {
    const float* x   = (const float*)d_in[0];
    const void*  ei  = d_in[1];
    const float* W1  = (const float*)d_in[2];
    const float* a1s = (const float*)d_in[3];
    const float* a1d = (const float*)d_in[4];
    const float* b1  = (const float*)d_in[5];
    const float* W2  = (const float*)d_in[6];
    const float* a2s = (const float*)d_in[7];
    const float* a2d = (const float*)d_in[8];
    const float* b2  = (const float*)d_in[9];
    const float* Wa  = (const float*)d_in[10];
    const float* ba  = (const float*)d_in[11];
    const float* Wc  = (const float*)d_in[12];
    const float* bc  = (const float*)d_in[13];
    float* out = (float*)d_out;

    int Nn   = in_sizes[0] / INDIM;
    int E    = in_sizes[1] / 2;
    int etot = E + Nn;

    prep_kernel<<<(Nn + 255) / 256, 256>>>((const unsigned int*)ei, out, Nn);
    count_kernel<<<(etot + 1023) / 1024, 256>>>(ei, E, etot);
    scan_kernel<<<1, 1024>>>(Nn, etot);
    gemm1_kernel<<<(Nn + 15) / 16, 128>>>(x, W1, a1s, a1d, Nn);   // 4th: profiled
    scatter_kernel<<<(etot + 1023) / 1024, 256>>>(ei, E, etot);

    attn1_kernel<<<(Nn * 32 + 255) / 256, 256>>>(b1, Nn);
    gemm2_kernel<<<(Nn * 8 + 255) / 256, 256>>>(W2, a2s, a2d, Nn);
    attn2_kernel<<<(Nn * 32 + 255) / 256, 256>>>(b2, Nn);
    heads_kernel<<<(Nn + 31) / 32, 1024>>>(Wa, ba, Wc, bc, out, Nn);
}

// round 7
// speedup vs baseline: 1.2376x; 1.1096x over previous
#include <cuda_runtime.h>
#include <cuda_fp16.h>
#include <math.h>

// ---------------------------------------------------------------------------
// Problem constants
// ---------------------------------------------------------------------------
#define MAXN   50000
#define MAXE   1048576
#define INDIM  128
#define HID    32
#define H1     4
#define C1     128
#define AGENTS 32
#define NEG    0.2f

// ---------------------------------------------------------------------------
// Device scratch
// ---------------------------------------------------------------------------
__device__ __align__(16) __half g_h1h[MAXN * C1];  // layer1 feats (fp16)
__device__ __align__(16) float g_x1 [MAXN * C1];   // layer1 out (biased+elu)
__device__ __align__(16) float g_as1[MAXN * H1];
__device__ __align__(16) float g_ad1[MAXN * H1];
__device__ __align__(16) __half g_h2h[MAXN * HID]; // layer2 feats (fp16)
__device__ __align__(16) float g_o2 [MAXN * HID];
__device__ float g_as2[MAXN];
__device__ float g_ad2[MAXN];
__device__ int   g_cnt[MAXN];
__device__ int   g_rowstart[MAXN + 1];
__device__ int   g_rowcur[MAXN];
__device__ int   g_csr[MAXE];
__device__ int   g_is64;

// ---------------------------------------------------------------------------
// Helpers
// ---------------------------------------------------------------------------
__device__ __forceinline__ float lrelu(float v) { return v > 0.f ? v : NEG * v; }
__device__ __forceinline__ float elu(float v)   { return v > 0.f ? v : expm1f(v); }

__device__ __forceinline__ int load_dst(const void* __restrict__ ei, int i, int E) {
    if (i >= E) return i - E;
    return g_is64 ? (int)((const long long*)ei)[E + i] : ((const int*)ei)[E + i];
}
__device__ __forceinline__ int load_src(const void* __restrict__ ei, int i, int E) {
    if (i >= E) return i - E;
    return g_is64 ? (int)((const long long*)ei)[i] : ((const int*)ei)[i];
}

// ---------------------------------------------------------------------------
// prep: zero counts + value cell + int64 probe
// ---------------------------------------------------------------------------
__global__ void prep_kernel(const unsigned int* __restrict__ w,
                            float* __restrict__ out, int Nn) {
    int i = blockIdx.x * blockDim.x + threadIdx.x;
    if (i < Nn) g_cnt[i] = 0;
    if (i == 0) {
        out[(long long)AGENTS * Nn] = 0.f;
        int allz = 1;
        for (int k = 0; k < 16; k++)
            if (w[2 * k + 1] != 0u) allz = 0;
        g_is64 = allz;
    }
}

// ---------------------------------------------------------------------------
// CSR build
// ---------------------------------------------------------------------------
__global__ void count_kernel(const void* __restrict__ ei, int E, int etot) {
    int i0 = (blockIdx.x * blockDim.x + threadIdx.x) * 4;
#pragma unroll
    for (int k = 0; k < 4; k++) {
        int i = i0 + k;
        if (i < etot) atomicAdd(&g_cnt[load_dst(ei, i, E)], 1);
    }
}

__global__ __launch_bounds__(1024) void scan_kernel(int Nn, int etot) {
    __shared__ int wsum[32];
    int t = threadIdx.x;
    const int PER = (MAXN + 1023) / 1024;
    int lo = t * PER, hi = min(lo + PER, Nn);
    int sum = 0;
    for (int i = lo; i < hi; i++) sum += g_cnt[i];

    int lane = t & 31, w = t >> 5;
    int v = sum;
#pragma unroll
    for (int off = 1; off < 32; off <<= 1) {
        int u = __shfl_up_sync(0xffffffffu, v, off);
        if (lane >= off) v += u;
    }
    if (lane == 31) wsum[w] = v;
    __syncthreads();
    if (w == 0) {
        int u = wsum[lane];
#pragma unroll
        for (int off = 1; off < 32; off <<= 1) {
            int p = __shfl_up_sync(0xffffffffu, u, off);
            if (lane >= off) u += p;
        }
        wsum[lane] = u;
    }
    __syncthreads();
    int base = (w > 0 ? wsum[w - 1] : 0) + (v - sum);
    int run = base;
    for (int i = lo; i < hi; i++) {
        g_rowstart[i] = run;
        g_rowcur[i]   = run;
        run += g_cnt[i];
    }
    if (t == 1023) g_rowstart[Nn] = etot;
}

__global__ void scatter_kernel(const void* __restrict__ ei, int E, int etot) {
    int i0 = (blockIdx.x * blockDim.x + threadIdx.x) * 4;
#pragma unroll
    for (int k = 0; k < 4; k++) {
        int i = i0 + k;
        if (i < etot) {
            int d = load_dst(ei, i, E);
            int s = load_src(ei, i, E);
            int pos = atomicAdd(&g_rowcur[d], 1);
            g_csr[pos] = s;
        }
    }
}

// ---------------------------------------------------------------------------
// GEMM1: h1 = x @ W1 ([N,128]x[128,128]) fused a_s/a_d; h1 stored fp16.
// Block 128 thr = 32 nodes. Thread: 2 cols (c, c+64) x 16 nodes -> 32 acc.
// Per 8-k tile: 2 broadcast LDS.128 feed 16 FMA (ratio 8:1).
// ---------------------------------------------------------------------------
__global__ __launch_bounds__(128) void gemm1_kernel(
    const float* __restrict__ x, const float* __restrict__ W1,
    const float* __restrict__ a1s, const float* __restrict__ a1d, int Nn) {
    __shared__ float xs[32][INDIM];          // 16 KB
    int t  = threadIdx.x;
    int ng = t >> 6;                          // node half: 0/1
    int c  = t & 63;                          // cols c and c+64
    int n0 = blockIdx.x * 32;

    const float4* xv = (const float4*)x;
    for (int i = t; i < 32 * 32; i += 128) {
        int m = i >> 5, cc = i & 31;
        int n = n0 + m;
        float4 v = (n < Nn) ? xv[(long long)n * 32 + cc]
                            : make_float4(0.f, 0.f, 0.f, 0.f);
        ((float4*)(&xs[0][0]))[i] = v;
    }
    __syncthreads();

    float acc0[16], acc1[16];
#pragma unroll
    for (int m = 0; m < 16; m++) { acc0[m] = 0.f; acc1[m] = 0.f; }

    for (int kt = 0; kt < INDIM; kt += 8) {
        float w0[8], w1[8];
#pragma unroll
        for (int j = 0; j < 8; j++) {
            w0[j] = W1[(kt + j) * C1 + c];
            w1[j] = W1[(kt + j) * C1 + c + 64];
        }
#pragma unroll
        for (int m = 0; m < 16; m++) {
            const float4* xr = (const float4*)&xs[ng * 16 + m][kt];
            float4 xa = xr[0], xb = xr[1];
            acc0[m] += xa.x * w0[0] + xa.y * w0[1] + xa.z * w0[2] + xa.w * w0[3]
                     + xb.x * w0[4] + xb.y * w0[5] + xb.z * w0[6] + xb.w * w0[7];
            acc1[m] += xa.x * w1[0] + xa.y * w1[1] + xa.z * w1[2] + xa.w * w1[3]
                     + xb.x * w1[4] + xb.y * w1[5] + xb.z * w1[6] + xb.w * w1[7];
        }
    }

    // epilogue: warp covers cols [32w0,32w0+31] (head h0=c>>5) and +64 (h0+2)
    float as0 = a1s[c],      ad0 = a1d[c];
    float as1 = a1s[c + 64], ad1 = a1d[c + 64];
    int lane = t & 31;
    int h0 = (c >> 5);                        // 0 for warp {0,2}, 1 for {1,3}
#pragma unroll
    for (int m = 0; m < 16; m++) {
        int n = n0 + ng * 16 + m;
        if (n < Nn) {
            g_h1h[(long long)n * C1 + c]      = __float2half_rn(acc0[m]);
            g_h1h[(long long)n * C1 + c + 64] = __float2half_rn(acc1[m]);
        }
        float s0 = acc0[m] * as0, d0 = acc0[m] * ad0;
        float s1 = acc1[m] * as1, d1 = acc1[m] * ad1;
#pragma unroll
        for (int off = 16; off; off >>= 1) {
            s0 += __shfl_down_sync(0xffffffffu, s0, off);
            d0 += __shfl_down_sync(0xffffffffu, d0, off);
            s1 += __shfl_down_sync(0xffffffffu, s1, off);
            d1 += __shfl_down_sync(0xffffffffu, d1, off);
        }
        if (lane == 0 && n < Nn) {
            g_as1[n * H1 + h0]     = s0;
            g_ad1[n * H1 + h0]     = d0;
            g_as1[n * H1 + h0 + 2] = s1;
            g_ad1[n * H1 + h0 + 2] = d1;
        }
    }
}

// ---------------------------------------------------------------------------
// Layer1 attention, single pass, gather-side, warp/node (fp16 h1 gathers).
// ---------------------------------------------------------------------------
__global__ __launch_bounds__(256) void attn1_kernel(
    const float* __restrict__ b1, int Nn) {
    __shared__ float4 s_num[8][32];
    __shared__ int    s_src[8][32];
    int wg   = threadIdx.x >> 5;
    int warp = (blockIdx.x * blockDim.x + threadIdx.x) >> 5;
    int lane = threadIdx.x & 31;
    if (warp >= Nn) return;
    int start = g_rowstart[warp], end = g_rowstart[warp + 1];
    float4 adv = *(const float4*)(g_ad1 + warp * H1);
    int h = lane >> 3;

    float4 den = make_float4(0.f, 0.f, 0.f, 0.f);
    float ax = 0.f, ay = 0.f, az = 0.f, aw = 0.f;
    const uint2* h1 = (const uint2*)g_h1h;

    for (int base = start; base < end; base += 32) {
        int cnt = min(32, end - base);
        int s = 0;
        float4 nm = make_float4(0.f, 0.f, 0.f, 0.f);
        if (lane < cnt) {
            s = g_csr[base + lane];
            float4 av = *(const float4*)(g_as1 + s * H1);
            nm.x = __expf(lrelu(av.x + adv.x));
            nm.y = __expf(lrelu(av.y + adv.y));
            nm.z = __expf(lrelu(av.z + adv.z));
            nm.w = __expf(lrelu(av.w + adv.w));
            den.x += nm.x; den.y += nm.y; den.z += nm.z; den.w += nm.w;
        }
        s_num[wg][lane] = nm;
        s_src[wg][lane] = s;
        __syncwarp();

        int j = 0;
        for (; j + 2 <= cnt; j += 2) {
            int sj0 = s_src[wg][j];
            int sj1 = s_src[wg][j + 1];
            float a0 = ((const float*)&s_num[wg][j])[h];
            float a1 = ((const float*)&s_num[wg][j + 1])[h];
            uint2 u0 = h1[(long long)sj0 * 32 + lane];
            uint2 u1 = h1[(long long)sj1 * 32 + lane];
            float2 f00 = __half22float2(*(const __half2*)&u0.x);
            float2 f01 = __half22float2(*(const __half2*)&u0.y);
            float2 f10 = __half22float2(*(const __half2*)&u1.x);
            float2 f11 = __half22float2(*(const __half2*)&u1.y);
            ax += a0 * f00.x + a1 * f10.x;
            ay += a0 * f00.y + a1 * f10.y;
            az += a0 * f01.x + a1 * f11.x;
            aw += a0 * f01.y + a1 * f11.y;
        }
        if (j < cnt) {
            int sj0 = s_src[wg][j];
            float a0 = ((const float*)&s_num[wg][j])[h];
            uint2 u0 = h1[(long long)sj0 * 32 + lane];
            float2 f00 = __half22float2(*(const __half2*)&u0.x);
            float2 f01 = __half22float2(*(const __half2*)&u0.y);
            ax += a0 * f00.x; ay += a0 * f00.y;
            az += a0 * f01.x; aw += a0 * f01.y;
        }
        __syncwarp();
    }

#pragma unroll
    for (int off = 16; off; off >>= 1) {
        den.x += __shfl_xor_sync(0xffffffffu, den.x, off);
        den.y += __shfl_xor_sync(0xffffffffu, den.y, off);
        den.z += __shfl_xor_sync(0xffffffffu, den.z, off);
        den.w += __shfl_xor_sync(0xffffffffu, den.w, off);
    }
    float dh = (h == 0) ? den.x : (h == 1) ? den.y : (h == 2) ? den.z : den.w;
    float rden = 1.f / dh;

    float4 bb = ((const float4*)b1)[lane];
    float4 o;
    o.x = elu(ax * rden + bb.x); o.y = elu(ay * rden + bb.y);
    o.z = elu(az * rden + bb.z); o.w = elu(aw * rden + bb.w);
    ((float4*)g_x1)[(long long)warp * 32 + lane] = o;
}

// ---------------------------------------------------------------------------
// GEMM2: h2 = x1 @ W2 ([N,128]x[128,32]) fused a_s/a_d; h2 stored fp16.
// Block 128 thr = 32 nodes. Thread: col c (0-31) x 8 nodes (group g).
// Per 8-k tile: 2 broadcast LDS.128 feed 8 FMA.
// ---------------------------------------------------------------------------
__global__ __launch_bounds__(128) void gemm2_kernel(
    const float* __restrict__ W2, const float* __restrict__ a2s,
    const float* __restrict__ a2d, int Nn) {
    __shared__ float xs[32][C1];             // 16 KB
    int t = threadIdx.x;
    int g = t >> 5;                           // node group 0-3 (8 nodes)
    int c = t & 31;                           // output col
    int n0 = blockIdx.x * 32;

    const float4* xv = (const float4*)g_x1;
    for (int i = t; i < 32 * 32; i += 128) {
        int m = i >> 5, cc = i & 31;
        int n = n0 + m;
        float4 v = (n < Nn) ? xv[(long long)n * 32 + cc]
                            : make_float4(0.f, 0.f, 0.f, 0.f);
        ((float4*)(&xs[0][0]))[i] = v;
    }
    __syncthreads();

    float acc[8];
#pragma unroll
    for (int m = 0; m < 8; m++) acc[m] = 0.f;

    for (int kt = 0; kt < C1; kt += 8) {
        float w[8];
#pragma unroll
        for (int j = 0; j < 8; j++) w[j] = W2[(kt + j) * HID + c];
#pragma unroll
        for (int m = 0; m < 8; m++) {
            const float4* xr = (const float4*)&xs[g * 8 + m][kt];
            float4 xa = xr[0], xb = xr[1];
            acc[m] += xa.x * w[0] + xa.y * w[1] + xa.z * w[2] + xa.w * w[3]
                    + xb.x * w[4] + xb.y * w[5] + xb.z * w[6] + xb.w * w[7];
        }
    }

    float asv = a2s[c], adv = a2d[c];
#pragma unroll
    for (int m = 0; m < 8; m++) {
        int n = n0 + g * 8 + m;
        if (n < Nn) g_h2h[(long long)n * HID + c] = __float2half_rn(acc[m]);
        float s = acc[m] * asv;
        float d = acc[m] * adv;
#pragma unroll
        for (int off = 16; off; off >>= 1) {
            s += __shfl_down_sync(0xffffffffu, s, off);
            d += __shfl_down_sync(0xffffffffu, d, off);
        }
        if (c == 0 && n < Nn) { g_as2[n] = s; g_ad2[n] = d; }
    }
}

// ---------------------------------------------------------------------------
// Layer2 attention, single pass, warp/node, lane = feature (fp16 h2).
// ---------------------------------------------------------------------------
__global__ __launch_bounds__(256) void attn2_kernel(
    const float* __restrict__ b2, int Nn) {
    __shared__ float s_num[8][32];
    __shared__ int   s_src[8][32];
    int wg   = threadIdx.x >> 5;
    int warp = (blockIdx.x * blockDim.x + threadIdx.x) >> 5;
    int lane = threadIdx.x & 31;
    if (warp >= Nn) return;
    int start = g_rowstart[warp], end = g_rowstart[warp + 1];
    float adn = g_ad2[warp];

    float den = 0.f, acc = 0.f;
    for (int base = start; base < end; base += 32) {
        int cnt = min(32, end - base);
        int s = 0; float num = 0.f;
        if (lane < cnt) {
            s = g_csr[base + lane];
            num = __expf(lrelu(g_as2[s] + adn));
            den += num;
        }
        s_num[wg][lane] = num;
        s_src[wg][lane] = s;
        __syncwarp();

        int j = 0;
        for (; j + 2 <= cnt; j += 2) {
            int sj0 = s_src[wg][j], sj1 = s_src[wg][j + 1];
            float a0 = s_num[wg][j], a1 = s_num[wg][j + 1];
            float v0 = __half2float(g_h2h[(long long)sj0 * HID + lane]);
            float v1 = __half2float(g_h2h[(long long)sj1 * HID + lane]);
            acc += a0 * v0 + a1 * v1;
        }
        if (j < cnt) {
            int sj0 = s_src[wg][j];
            acc += s_num[wg][j] * __half2float(g_h2h[(long long)sj0 * HID + lane]);
        }
        __syncwarp();
    }
#pragma unroll
    for (int off = 16; off; off >>= 1)
        den += __shfl_xor_sync(0xffffffffu, den, off);
    g_o2[(long long)warp * HID + lane] = elu(acc / den + b2[lane]);
}

// ---------------------------------------------------------------------------
// Actor/critic heads.
// ---------------------------------------------------------------------------
__global__ __launch_bounds__(1024) void heads_kernel(
    const float* __restrict__ Wa, const float* __restrict__ ba,
    const float* __restrict__ Wc, const float* __restrict__ bc,
    float* __restrict__ out, int Nn) {
    __shared__ float Was[AGENTS * HID];
    __shared__ float tile[32][33];
    __shared__ float warr[32];
    int t = threadIdx.x;
    Was[t & (AGENTS * HID - 1)] = Wa[t & (AGENTS * HID - 1)];
    __syncthreads();

    int w = t >> 5, lane = t & 31;
    int n = blockIdx.x * 32 + w;
    float hv = (n < Nn) ? g_o2[(long long)n * HID + lane] : 0.f;

    float acc = 0.f;
    float vs = hv * Wc[lane];
#pragma unroll
    for (int f = 0; f < HID; f++) {
        float xv = __shfl_sync(0xffffffffu, hv, f);
        acc += xv * Was[f * AGENTS + lane];
    }
    tile[w][lane] = acc + ba[lane];
#pragma unroll
    for (int off = 16; off; off >>= 1) vs += __shfl_down_sync(0xffffffffu, vs, off);
    if (lane == 0) warr[w] = vs;
    __syncthreads();

    int n2 = blockIdx.x * 32 + lane;
    if (n2 < Nn) out[(long long)w * Nn + n2] = tile[lane][w];

    if (t == 0) {
        float bs = 0.f;
#pragma unroll
        for (int i = 0; i < 32; i++) bs += warr[i];
        atomicAdd(out + (long long)AGENTS * Nn, bs / (float)Nn);
        if (blockIdx.x == 0) atomicAdd(out + (long long)AGENTS * Nn, bc[0]);
    }
}

// ---------------------------------------------------------------------------
// Launch (gemm1 kept 4th: the ncu sample slot)
// ---------------------------------------------------------------------------
extern "C" void kernel_launch(void* const* d_in, const int* in_sizes, int n_in,
                              void* d_out, int out_size) {
    const float* x   = (const float*)d_in[0];
    const void*  ei  = d_in[1];
    const float* W1  = (const float*)d_in[2];
    const float* a1s = (const float*)d_in[3];
    const float* a1d = (const float*)d_in[4];
    const float* b1  = (const float*)d_in[5];
    const float* W2  = (const float*)d_in[6];
    const float* a2s = (const float*)d_in[7];
    const float* a2d = (const float*)d_in[8];
    const float* b2  = (const float*)d_in[9];
    const float* Wa  = (const float*)d_in[10];
    const float* ba  = (const float*)d_in[11];
    const float* Wc  = (const float*)d_in[12];
    const float* bc  = (const float*)d_in[13];
    float* out = (float*)d_out;

    int Nn   = in_sizes[0] / INDIM;
    int E    = in_sizes[1] / 2;
    int etot = E + Nn;

    prep_kernel<<<(Nn + 255) / 256, 256>>>((const unsigned int*)ei, out, Nn);
    count_kernel<<<(etot + 1023) / 1024, 256>>>(ei, E, etot);
    scan_kernel<<<1, 1024>>>(Nn, etot);
    gemm1_kernel<<<(Nn + 31) / 32, 128>>>(x, W1, a1s, a1d, Nn);   // 4th: profiled
    scatter_kernel<<<(etot + 1023) / 1024, 256>>>(ei, E, etot);

    attn1_kernel<<<(Nn * 32 + 255) / 256, 256>>>(b1, Nn);
    gemm2_kernel<<<(Nn + 31) / 32, 128>>>(W2, a2s, a2d, Nn);
    attn2_kernel<<<(Nn * 32 + 255) / 256, 256>>>(b2, Nn);
    heads_kernel<<<(Nn + 31) / 32, 1024>>>(Wa, ba, Wc, bc, out, Nn);
}